// round 1
// baseline (speedup 1.0000x reference)
#include <cuda_runtime.h>
#include <math.h>

#define B_ 4
#define T_ 8
#define C_ 128
#define HW_ 9216          // 96*96
#define NBT 32            // B*T
#define NCHUNK 72
#define CHUNK 16384       // 72*16384 = 1179648 = C*HW
#define TILEP 32
#define NTILE 288         // HW_/TILEP

// deterministic scratch (fixed slots, no atomics)
__device__ float g_psum[NBT * NCHUNK];
__device__ float g_psq [NBT * NCHUNK];
__device__ float g_A[NBT * C_];   // per (b,t,c): xn = x*A + Bc
__device__ float g_Bc[NBT * C_];

// ---------------- Kernel 1: partial sums per (b,t) chunk ----------------
__global__ __launch_bounds__(256) void reduce_kernel(const float* __restrict__ x,
                                                     const float* __restrict__ pos) {
    int bt    = blockIdx.x / NCHUNK;
    int chunk = blockIdx.x % NCHUNK;
    int t     = bt & (T_ - 1);
    const float4* x4 = (const float4*)(x + (size_t)bt * C_ * HW_);
    int base4 = chunk * (CHUNK / 4);
    float s = 0.f, sq = 0.f;
#pragma unroll
    for (int i = 0; i < 16; i++) {
        int e4 = base4 + i * 256 + threadIdx.x;
        int c  = e4 / 2304;                 // 2304 float4 per channel
        float pv = pos[t * C_ + c];
        float4 v = x4[e4];
        float a0 = v.x + pv, a1 = v.y + pv, a2 = v.z + pv, a3 = v.w + pv;
        s  += (a0 + a1) + (a2 + a3);
        sq += (a0 * a0 + a1 * a1) + (a2 * a2 + a3 * a3);
    }
    __shared__ float ss[8], ssq[8];
#pragma unroll
    for (int o = 16; o; o >>= 1) {
        s  += __shfl_down_sync(0xFFFFFFFFu, s, o);
        sq += __shfl_down_sync(0xFFFFFFFFu, sq, o);
    }
    int w = threadIdx.x >> 5;
    if ((threadIdx.x & 31) == 0) { ss[w] = s; ssq[w] = sq; }
    __syncthreads();
    if (threadIdx.x == 0) {
        float S = 0.f, SQ = 0.f;
#pragma unroll
        for (int i = 0; i < 8; i++) { S += ss[i]; SQ += ssq[i]; }
        g_psum[bt * NCHUNK + chunk] = S;
        g_psq [bt * NCHUNK + chunk] = SQ;
    }
}

// ---------------- Kernel 2: finalize mean/rstd -> affine A,B ----------------
__global__ __launch_bounds__(256) void finalize_kernel(const float* __restrict__ pos,
                                                       const float* __restrict__ nw,
                                                       const float* __restrict__ nb) {
    __shared__ float sm[NBT], sr[NBT];
    int tid = threadIdx.x;
    if (tid < NBT) {
        float S = 0.f, SQ = 0.f;
        for (int i = 0; i < NCHUNK; i++) { S += g_psum[tid * NCHUNK + i]; SQ += g_psq[tid * NCHUNK + i]; }
        const float invN = 1.0f / (float)(C_ * HW_);
        float mean = S * invN;
        float var  = SQ * invN - mean * mean;
        sm[tid] = mean;
        sr[tid] = rsqrtf(var + 1e-5f);
    }
    __syncthreads();
    for (int idx = tid; idx < NBT * C_; idx += 256) {
        int bt = idx >> 7, c = idx & 127, t = bt & (T_ - 1);
        float a = sr[bt] * nw[c];
        g_A[idx]  = a;
        g_Bc[idx] = (pos[t * C_ + c] - sm[bt]) * a + nb[c];
    }
}

// ---------------- Kernel 3: fused q/kv/attention/proj ----------------
// smem layout (floats)
#define SM_XN   0                    // 128*32
#define SM_KV   (SM_XN + 128*32)     // 256*32  (k: 0..127, v: 128..255)
#define SM_Q    (SM_KV + 256*32)     // 128*32
#define SM_O    (SM_Q  + 128*32)     // 128*32
#define SM_M    (SM_O  + 128*32)     // 128
#define SM_SUM  (SM_M   + 128)       // 128
#define SM_CORR (SM_SUM + 128)       // 128
#define SM_WS   (SM_CORR+ 128)       // 128
#define SMEM_FLOATS (SM_WS + 128)
#define SMEM_BYTES (SMEM_FLOATS * 4)

__global__ __launch_bounds__(256) void main_kernel(const float* __restrict__ x,
                                                   const float* __restrict__ qkv_w,
                                                   const float* __restrict__ proj_w,
                                                   float* __restrict__ out) {
    extern __shared__ float sm[];
    float* sXN = sm + SM_XN;
    float* sKV = sm + SM_KV;
    float* sQ  = sm + SM_Q;
    float* sO  = sm + SM_O;
    float* sM  = sm + SM_M;
    float* sSum= sm + SM_SUM;
    float* sCorr = sm + SM_CORR;
    float* sWs   = sm + SM_WS;

    int b    = blockIdx.x / NTILE;
    int tile = blockIdx.x % NTILE;
    int hw0  = tile * TILEP;
    int tid  = threadIdx.x;
    int dg   = tid >> 3;   // 0..31
    int pg   = tid & 7;    // 0..7 -> pixels pg*4..pg*4+3

    // init state
    for (int i = tid; i < 128 * 32; i += 256) sO[i] = 0.f;
    if (tid < 128) { sM[tid] = -1e30f; sSum[tid] = 0.f; }

    // ---- load normalized tile for t = T-1, compute Q ----
    {
        int bt = b * T_ + (T_ - 1);
        const float* xb = x + (size_t)bt * C_ * HW_;
        const float* Ab = g_A  + bt * C_;
        const float* Bb = g_Bc + bt * C_;
#pragma unroll
        for (int i = tid; i < 128 * 32; i += 256) {
            int c = i >> 5, p = i & 31;
            sXN[i] = xb[c * HW_ + hw0 + p] * Ab[c] + Bb[c];
        }
    }
    __syncthreads();
    {
        // 128 dims x 32 pix: thread tile 4x4
        float acc[4][4] = {};
        const float* wb = qkv_w + (size_t)(dg * 4) * C_;
#pragma unroll 4
        for (int k = 0; k < 128; k += 4) {
            float xr[4][4];
#pragma unroll
            for (int kk = 0; kk < 4; kk++) {
                float4 v = *(const float4*)(sXN + (k + kk) * 32 + pg * 4);
                xr[kk][0] = v.x; xr[kk][1] = v.y; xr[kk][2] = v.z; xr[kk][3] = v.w;
            }
#pragma unroll
            for (int i = 0; i < 4; i++) {
                float4 wv = *(const float4*)(wb + i * C_ + k);
                float wr[4] = {wv.x, wv.y, wv.z, wv.w};
#pragma unroll
                for (int kk = 0; kk < 4; kk++)
#pragma unroll
                    for (int j = 0; j < 4; j++)
                        acc[i][j] = fmaf(wr[kk], xr[kk][j], acc[i][j]);
            }
        }
        const float scale = 0.17677669529663687f;  // 32^-0.5 folded into q
#pragma unroll
        for (int i = 0; i < 4; i++) {
            float4 o; o.x = acc[i][0]*scale; o.y = acc[i][1]*scale; o.z = acc[i][2]*scale; o.w = acc[i][3]*scale;
            *(float4*)(sQ + (dg * 4 + i) * 32 + pg * 4) = o;
        }
    }
    __syncthreads();

    // ---- stream s = 0..7: kv GEMM + online softmax ----
    for (int s = 0; s < T_; s++) {
        {
            int bt = b * T_ + s;
            const float* xb = x + (size_t)bt * C_ * HW_;
            const float* Ab = g_A  + bt * C_;
            const float* Bb = g_Bc + bt * C_;
#pragma unroll
            for (int i = tid; i < 128 * 32; i += 256) {
                int c = i >> 5, p = i & 31;
                sXN[i] = xb[c * HW_ + hw0 + p] * Ab[c] + Bb[c];
            }
        }
        __syncthreads();

        // KV GEMM: 256 dims x 32 pix, thread tile 8x4. Row of qkv_w = 128 + d for d in 0..255.
        {
            float acc[8][4] = {};
            const float* wb = qkv_w + (size_t)(128 + dg * 8) * C_;
#pragma unroll 4
            for (int k = 0; k < 128; k += 4) {
                float xr[4][4];
#pragma unroll
                for (int kk = 0; kk < 4; kk++) {
                    float4 v = *(const float4*)(sXN + (k + kk) * 32 + pg * 4);
                    xr[kk][0] = v.x; xr[kk][1] = v.y; xr[kk][2] = v.z; xr[kk][3] = v.w;
                }
#pragma unroll
                for (int i = 0; i < 8; i++) {
                    float4 wv = *(const float4*)(wb + i * C_ + k);
                    float wr[4] = {wv.x, wv.y, wv.z, wv.w};
#pragma unroll
                    for (int kk = 0; kk < 4; kk++)
#pragma unroll
                        for (int j = 0; j < 4; j++)
                            acc[i][j] = fmaf(wr[kk], xr[kk][j], acc[i][j]);
                }
            }
#pragma unroll
            for (int i = 0; i < 8; i++) {
                float4 o; o.x = acc[i][0]; o.y = acc[i][1]; o.z = acc[i][2]; o.w = acc[i][3];
                *(float4*)(sKV + (dg * 8 + i) * 32 + pg * 4) = o;
            }
        }
        __syncthreads();

        // logits (q . k, q pre-scaled) + online softmax state, 128 (head,pixel) pairs
        if (tid < 128) {
            int h = tid >> 5, p = tid & 31;
            float lg = 0.f;
#pragma unroll
            for (int dd = 0; dd < 32; dd++)
                lg = fmaf(sQ[(h * 32 + dd) * 32 + p], sKV[(h * 32 + dd) * 32 + p], lg);
            float mo = sM[tid];
            float mn = fmaxf(mo, lg);
            float corr = expf(mo - mn);
            float ws   = expf(lg - mn);
            sSum[tid] = sSum[tid] * corr + ws;
            sM[tid]   = mn;
            sCorr[tid] = corr;
            sWs[tid]   = ws;
        }
        __syncthreads();

        // O update: O = O*corr + ws * v
#pragma unroll
        for (int j = 0; j < 16; j++) {
            int idx = tid + j * 256;
            int hp  = ((idx >> 10) << 5) | (idx & 31);   // h*32 + p
            sO[idx] = sO[idx] * sCorr[hp] + sWs[hp] * sKV[4096 + idx];
        }
        __syncthreads();
    }

    // normalize O by softmax denominator
    if (tid < 128) sCorr[tid] = 1.0f / sSum[tid];
    __syncthreads();
#pragma unroll
    for (int j = 0; j < 16; j++) {
        int idx = tid + j * 256;
        int hp  = ((idx >> 10) << 5) | (idx & 31);
        sO[idx] *= sCorr[hp];
    }
    __syncthreads();

    // ---- projection GEMM: out2[d][p] = sum_c proj_w[d][c] * O[c][p], thread tile 4x4 ----
    {
        float acc[4][4] = {};
        const float* wb = proj_w + (size_t)(dg * 4) * C_;
#pragma unroll 4
        for (int k = 0; k < 128; k += 4) {
            float xr[4][4];
#pragma unroll
            for (int kk = 0; kk < 4; kk++) {
                float4 v = *(const float4*)(sO + (k + kk) * 32 + pg * 4);
                xr[kk][0] = v.x; xr[kk][1] = v.y; xr[kk][2] = v.z; xr[kk][3] = v.w;
            }
#pragma unroll
            for (int i = 0; i < 4; i++) {
                float4 wv = *(const float4*)(wb + i * C_ + k);
                float wr[4] = {wv.x, wv.y, wv.z, wv.w};
#pragma unroll
                for (int kk = 0; kk < 4; kk++)
#pragma unroll
                    for (int j = 0; j < 4; j++)
                        acc[i][j] = fmaf(wr[kk], xr[kk][j], acc[i][j]);
            }
        }
#pragma unroll
        for (int i = 0; i < 4; i++) {
            float4 o; o.x = acc[i][0]; o.y = acc[i][1]; o.z = acc[i][2]; o.w = acc[i][3];
            *(float4*)(out + ((size_t)b * C_ + dg * 4 + i) * HW_ + hw0 + pg * 4) = o;
        }
    }
}

extern "C" void kernel_launch(void* const* d_in, const int* in_sizes, int n_in,
                              void* d_out, int out_size) {
    const float* x    = (const float*)d_in[0];
    const float* pos  = (const float*)d_in[1];
    const float* nw   = (const float*)d_in[2];
    const float* nb   = (const float*)d_in[3];
    const float* qkvw = (const float*)d_in[4];
    const float* pw   = (const float*)d_in[5];
    float* out = (float*)d_out;

    reduce_kernel<<<NBT * NCHUNK, 256>>>(x, pos);
    finalize_kernel<<<1, 256>>>(pos, nw, nb);
    cudaFuncSetAttribute(main_kernel, cudaFuncAttributeMaxDynamicSharedMemorySize, SMEM_BYTES);
    main_kernel<<<B_ * NTILE, 256, SMEM_BYTES>>>(x, qkvw, pw, out);
}

// round 2
// speedup vs baseline: 2.4817x; 2.4817x over previous
#include <cuda_runtime.h>
#include <math.h>

#define B_ 4
#define T_ 8
#define C_ 128
#define HW_ 9216          // 96*96
#define NBT 32            // B*T
#define NCHUNK 72
#define CHUNK 16384
#define TILEP 32
#define NTILE 288         // HW_/TILEP

// deterministic scratch
__device__ float g_psum[NBT * NCHUNK];
__device__ float g_psq [NBT * NCHUNK];
__device__ float g_A[NBT * C_];
__device__ float g_Bc[NBT * C_];
__device__ float g_WkT[C_ * C_];   // [c][h*32+d] = qkv_w[128 + h*32+d][c]

// ---------------- Kernel 1: partial sums per (b,t) chunk ----------------
__global__ __launch_bounds__(256) void reduce_kernel(const float* __restrict__ x,
                                                     const float* __restrict__ pos) {
    int bt    = blockIdx.x / NCHUNK;
    int chunk = blockIdx.x % NCHUNK;
    int t     = bt & (T_ - 1);
    const float4* x4 = (const float4*)(x + (size_t)bt * C_ * HW_);
    int base4 = chunk * (CHUNK / 4);
    float s = 0.f, sq = 0.f;
#pragma unroll
    for (int i = 0; i < 16; i++) {
        int e4 = base4 + i * 256 + threadIdx.x;
        int c  = e4 / 2304;
        float pv = pos[t * C_ + c];
        float4 v = x4[e4];
        float a0 = v.x + pv, a1 = v.y + pv, a2 = v.z + pv, a3 = v.w + pv;
        s  += (a0 + a1) + (a2 + a3);
        sq += (a0 * a0 + a1 * a1) + (a2 * a2 + a3 * a3);
    }
    __shared__ float ss[8], ssq[8];
#pragma unroll
    for (int o = 16; o; o >>= 1) {
        s  += __shfl_down_sync(0xFFFFFFFFu, s, o);
        sq += __shfl_down_sync(0xFFFFFFFFu, sq, o);
    }
    int w = threadIdx.x >> 5;
    if ((threadIdx.x & 31) == 0) { ss[w] = s; ssq[w] = sq; }
    __syncthreads();
    if (threadIdx.x == 0) {
        float S = 0.f, SQ = 0.f;
#pragma unroll
        for (int i = 0; i < 8; i++) { S += ss[i]; SQ += ssq[i]; }
        g_psum[bt * NCHUNK + chunk] = S;
        g_psq [bt * NCHUNK + chunk] = SQ;
    }
}

// ---------------- Kernel 2: finalize mean/rstd -> affine A,B ----------------
__global__ __launch_bounds__(256) void finalize_kernel(const float* __restrict__ pos,
                                                       const float* __restrict__ nw,
                                                       const float* __restrict__ nb) {
    __shared__ float sm[NBT], sr[NBT];
    int tid = threadIdx.x;
    if (tid < NBT) {
        float S = 0.f, SQ = 0.f;
        for (int i = 0; i < NCHUNK; i++) { S += g_psum[tid * NCHUNK + i]; SQ += g_psq[tid * NCHUNK + i]; }
        const float invN = 1.0f / (float)(C_ * HW_);
        float mean = S * invN;
        float var  = SQ * invN - mean * mean;
        sm[tid] = mean;
        sr[tid] = rsqrtf(var + 1e-5f);
    }
    __syncthreads();
    for (int idx = tid; idx < NBT * C_; idx += 256) {
        int bt = idx >> 7, c = idx & 127, t = bt & (T_ - 1);
        float a = sr[bt] * nw[c];
        g_A[idx]  = a;
        g_Bc[idx] = (pos[t * C_ + c] - sm[bt]) * a + nb[c];
    }
}

// ---------------- Kernel 2b: transpose Wk ----------------
__global__ __launch_bounds__(256) void wkT_kernel(const float* __restrict__ qkv_w) {
    int i = blockIdx.x * 256 + threadIdx.x;   // 0..16383
    int c = i >> 7, hd = i & 127;
    g_WkT[c * 128 + hd] = qkv_w[(128 + hd) * 128 + c];
}

// ---------------- Kernel 3: fused main ----------------
// smem float offsets
#define SM_XN   0                     // 128*32 = 4096
#define SM_BIG  4096                  // 4*128*32 = 16384  (U, then XBAR)
#define SM_Q    20480                 // 128*32 (Q, then OUT)
#define SM_L    24576                 // 8*128 = 1024 (logits -> attn weights)
#define SM_P    25600                 // 1024 partials
#define SMEM_FLOATS 26624
#define SMEM_BYTES (SMEM_FLOATS * 4)  // 106496

__global__ __launch_bounds__(256) void main_kernel(const float* __restrict__ x,
                                                   const float* __restrict__ qkv_w,
                                                   const float* __restrict__ proj_w,
                                                   float* __restrict__ out) {
    extern __shared__ float sm[];
    float* sXN  = sm + SM_XN;
    float* sBig = sm + SM_BIG;
    float* sQ   = sm + SM_Q;
    float* sL   = sm + SM_L;
    float* sP   = sm + SM_P;

    int b    = blockIdx.x / NTILE;
    int tile = blockIdx.x % NTILE;
    int hw0  = tile * TILEP;
    int tid  = threadIdx.x;
    int dg   = tid >> 3;   // 0..31
    int pg   = tid & 7;    // 0..7

    // ---- Phase A: normalized tile at t=T-1, then Q GEMM (scaled) ----
    {
        int bt = b * T_ + (T_ - 1);
        const float* xb = x + (size_t)bt * C_ * HW_;
        const float* Ab = g_A  + bt * C_;
        const float* Bb = g_Bc + bt * C_;
#pragma unroll
        for (int i = tid; i < 4096; i += 256) {
            int c = i >> 5, p = i & 31;
            sXN[i] = xb[c * HW_ + hw0 + p] * Ab[c] + Bb[c];
        }
    }
    __syncthreads();
    {
        float acc[4][4] = {};
        const float* wb = qkv_w + (size_t)(dg * 4) * C_;
#pragma unroll 4
        for (int k = 0; k < 128; k += 4) {
            float xr[4][4];
#pragma unroll
            for (int kk = 0; kk < 4; kk++) {
                float4 v = *(const float4*)(sXN + (k + kk) * 32 + pg * 4);
                xr[kk][0] = v.x; xr[kk][1] = v.y; xr[kk][2] = v.z; xr[kk][3] = v.w;
            }
#pragma unroll
            for (int i = 0; i < 4; i++) {
                float4 wv = *(const float4*)(wb + i * C_ + k);
                float wr[4] = {wv.x, wv.y, wv.z, wv.w};
#pragma unroll
                for (int kk = 0; kk < 4; kk++)
#pragma unroll
                    for (int j = 0; j < 4; j++)
                        acc[i][j] = fmaf(wr[kk], xr[kk][j], acc[i][j]);
            }
        }
        const float scale = 0.17677669529663687f;   // 32^-0.5 folded into Q
#pragma unroll
        for (int i = 0; i < 4; i++) {
            float4 o; o.x = acc[i][0]*scale; o.y = acc[i][1]*scale; o.z = acc[i][2]*scale; o.w = acc[i][3]*scale;
            *(float4*)(sQ + (dg * 4 + i) * 32 + pg * 4) = o;
        }
    }
    __syncthreads();

    // ---- Phase B: U_h[c][p] = sum_d WkT[c][h*32+d] * Q[h*32+d][p]  -> sBig ----
    {
        int cg = dg;   // 0..31, 4 c-rows each
#pragma unroll
        for (int h = 0; h < 4; h++) {
            float acc[4][4] = {};
#pragma unroll
            for (int d4 = 0; d4 < 32; d4 += 4) {
                float xr[4][4];
#pragma unroll
                for (int kk = 0; kk < 4; kk++) {
                    float4 v = *(const float4*)(sQ + (h * 32 + d4 + kk) * 32 + pg * 4);
                    xr[kk][0] = v.x; xr[kk][1] = v.y; xr[kk][2] = v.z; xr[kk][3] = v.w;
                }
#pragma unroll
                for (int i = 0; i < 4; i++) {
                    float4 wv = *(const float4*)(g_WkT + (cg * 4 + i) * 128 + h * 32 + d4);
                    float wr[4] = {wv.x, wv.y, wv.z, wv.w};
#pragma unroll
                    for (int kk = 0; kk < 4; kk++)
#pragma unroll
                        for (int j = 0; j < 4; j++)
                            acc[i][j] = fmaf(wr[kk], xr[kk][j], acc[i][j]);
                }
            }
#pragma unroll
            for (int i = 0; i < 4; i++) {
                float4 o; o.x = acc[i][0]; o.y = acc[i][1]; o.z = acc[i][2]; o.w = acc[i][3];
                *(float4*)(sBig + h * 4096 + (cg * 4 + i) * 32 + pg * 4) = o;
            }
        }
    }
    __syncthreads();

    // ---- Phase C: pass 1, logits L[s][h][p] = sum_c XN_s[c][p] * U_h[c][p] ----
    for (int s = 0; s < T_; s++) {
        {
            int bt = b * T_ + s;
            const float* xb = x + (size_t)bt * C_ * HW_;
            const float* Ab = g_A  + bt * C_;
            const float* Bb = g_Bc + bt * C_;
#pragma unroll
            for (int i = tid; i < 4096; i += 256) {
                int c = i >> 5, p = i & 31;
                sXN[i] = xb[c * HW_ + hw0 + p] * Ab[c] + Bb[c];
            }
        }
        __syncthreads();
        {
            int p = tid & 31, g8 = tid >> 5;           // 8 c-groups of 16
            int c0 = g8 * 16;
            float lg[4] = {0.f, 0.f, 0.f, 0.f};
#pragma unroll
            for (int cc = 0; cc < 16; cc++) {
                float xv = sXN[(c0 + cc) * 32 + p];
#pragma unroll
                for (int h = 0; h < 4; h++)
                    lg[h] = fmaf(xv, sBig[h * 4096 + (c0 + cc) * 32 + p], lg[h]);
            }
#pragma unroll
            for (int h = 0; h < 4; h++) sP[g8 * 128 + h * 32 + p] = lg[h];
        }
        __syncthreads();
        if (tid < 128) {
            float L = 0.f;
#pragma unroll
            for (int g8 = 0; g8 < 8; g8++) L += sP[g8 * 128 + tid];
            sL[s * 128 + tid] = L;
        }
        __syncthreads();
    }

    // ---- softmax over s (exact) ----
    if (tid < 128) {
        float m = -1e30f;
#pragma unroll
        for (int s = 0; s < T_; s++) m = fmaxf(m, sL[s * 128 + tid]);
        float e[T_]; float sum = 0.f;
#pragma unroll
        for (int s = 0; s < T_; s++) { e[s] = expf(sL[s * 128 + tid] - m); sum += e[s]; }
        float inv = 1.0f / sum;
#pragma unroll
        for (int s = 0; s < T_; s++) sL[s * 128 + tid] = e[s] * inv;
    }
    __syncthreads();

    // ---- Phase D: pass 2, xbar_h[c][p] = sum_s a[s][h][p] * XN_s[c][p] (regs) ----
    {
        int g    = tid >> 7;          // 0..1 -> heads 2g, 2g+1
        int cg16 = (tid >> 3) & 15;   // 16 c-groups of 8
        int pgl  = tid & 7;
        float xb_[2][8][4];
#pragma unroll
        for (int h2 = 0; h2 < 2; h2++)
#pragma unroll
            for (int cc = 0; cc < 8; cc++)
#pragma unroll
                for (int j = 0; j < 4; j++) xb_[h2][cc][j] = 0.f;

        for (int s = T_ - 1; s >= 0; s--) {
            if (s != T_ - 1) {                 // sXN already holds s=7 from pass 1
                __syncthreads();
                int bt = b * T_ + s;
                const float* xb = x + (size_t)bt * C_ * HW_;
                const float* Ab = g_A  + bt * C_;
                const float* Bb = g_Bc + bt * C_;
#pragma unroll
                for (int i = tid; i < 4096; i += 256) {
                    int c = i >> 5, p = i & 31;
                    sXN[i] = xb[c * HW_ + hw0 + p] * Ab[c] + Bb[c];
                }
                __syncthreads();
            }
            float a[2][4];
#pragma unroll
            for (int h2 = 0; h2 < 2; h2++) {
                float4 av = *(const float4*)(sL + s * 128 + (g * 2 + h2) * 32 + pgl * 4);
                a[h2][0] = av.x; a[h2][1] = av.y; a[h2][2] = av.z; a[h2][3] = av.w;
            }
#pragma unroll
            for (int cc = 0; cc < 8; cc++) {
                float4 xv = *(const float4*)(sXN + (cg16 * 8 + cc) * 32 + pgl * 4);
                float xr[4] = {xv.x, xv.y, xv.z, xv.w};
#pragma unroll
                for (int h2 = 0; h2 < 2; h2++)
#pragma unroll
                    for (int j = 0; j < 4; j++)
                        xb_[h2][cc][j] = fmaf(a[h2][j], xr[j], xb_[h2][cc][j]);
            }
        }
        __syncthreads();   // U in sBig no longer needed; safe to overwrite
#pragma unroll
        for (int h2 = 0; h2 < 2; h2++)
#pragma unroll
            for (int cc = 0; cc < 8; cc++) {
                float4 o; o.x = xb_[h2][cc][0]; o.y = xb_[h2][cc][1]; o.z = xb_[h2][cc][2]; o.w = xb_[h2][cc][3];
                *(float4*)(sBig + (g * 2 + h2) * 4096 + (cg16 * 8 + cc) * 32 + pgl * 4) = o;
            }
    }
    __syncthreads();

    // ---- Phase E: Out[h*32+d][p] = sum_c Wv[h*32+d][c] * xbar_h[c][p]  -> sQ ----
    {
        int h = dg >> 3;
        const float* xsrc = sBig + h * 4096;
        const float* wb   = qkv_w + (size_t)(256 + dg * 4) * C_;
        float acc[4][4] = {};
#pragma unroll 4
        for (int k = 0; k < 128; k += 4) {
            float xr[4][4];
#pragma unroll
            for (int kk = 0; kk < 4; kk++) {
                float4 v = *(const float4*)(xsrc + (k + kk) * 32 + pg * 4);
                xr[kk][0] = v.x; xr[kk][1] = v.y; xr[kk][2] = v.z; xr[kk][3] = v.w;
            }
#pragma unroll
            for (int i = 0; i < 4; i++) {
                float4 wv = *(const float4*)(wb + i * C_ + k);
                float wr[4] = {wv.x, wv.y, wv.z, wv.w};
#pragma unroll
                for (int kk = 0; kk < 4; kk++)
#pragma unroll
                    for (int j = 0; j < 4; j++)
                        acc[i][j] = fmaf(wr[kk], xr[kk][j], acc[i][j]);
            }
        }
#pragma unroll
        for (int i = 0; i < 4; i++) {
            float4 o; o.x = acc[i][0]; o.y = acc[i][1]; o.z = acc[i][2]; o.w = acc[i][3];
            *(float4*)(sQ + (dg * 4 + i) * 32 + pg * 4) = o;
        }
    }
    __syncthreads();

    // ---- Phase F: projection, y[e][p] = sum_c P[e][c] * Out[c][p] ----
    {
        float acc[4][4] = {};
        const float* wb = proj_w + (size_t)(dg * 4) * C_;
#pragma unroll 4
        for (int k = 0; k < 128; k += 4) {
            float xr[4][4];
#pragma unroll
            for (int kk = 0; kk < 4; kk++) {
                float4 v = *(const float4*)(sQ + (k + kk) * 32 + pg * 4);
                xr[kk][0] = v.x; xr[kk][1] = v.y; xr[kk][2] = v.z; xr[kk][3] = v.w;
            }
#pragma unroll
            for (int i = 0; i < 4; i++) {
                float4 wv = *(const float4*)(wb + i * C_ + k);
                float wr[4] = {wv.x, wv.y, wv.z, wv.w};
#pragma unroll
                for (int kk = 0; kk < 4; kk++)
#pragma unroll
                    for (int j = 0; j < 4; j++)
                        acc[i][j] = fmaf(wr[kk], xr[kk][j], acc[i][j]);
            }
        }
#pragma unroll
        for (int i = 0; i < 4; i++) {
            float4 o; o.x = acc[i][0]; o.y = acc[i][1]; o.z = acc[i][2]; o.w = acc[i][3];
            *(float4*)(out + ((size_t)b * C_ + dg * 4 + i) * HW_ + hw0 + pg * 4) = o;
        }
    }
}

extern "C" void kernel_launch(void* const* d_in, const int* in_sizes, int n_in,
                              void* d_out, int out_size) {
    const float* x    = (const float*)d_in[0];
    const float* pos  = (const float*)d_in[1];
    const float* nw   = (const float*)d_in[2];
    const float* nb   = (const float*)d_in[3];
    const float* qkvw = (const float*)d_in[4];
    const float* pw   = (const float*)d_in[5];
    float* out = (float*)d_out;

    reduce_kernel<<<NBT * NCHUNK, 256>>>(x, pos);
    finalize_kernel<<<1, 256>>>(pos, nw, nb);
    wkT_kernel<<<64, 256>>>(qkvw);
    cudaFuncSetAttribute(main_kernel, cudaFuncAttributeMaxDynamicSharedMemorySize, SMEM_BYTES);
    main_kernel<<<B_ * NTILE, 256, SMEM_BYTES>>>(x, qkvw, pw, out);
}

// round 3
// speedup vs baseline: 2.9745x; 1.1986x over previous
#include <cuda_runtime.h>
#include <math.h>

#define B_ 4
#define T_ 8
#define C_ 128
#define HW_ 9216          // 96*96
#define NBT 32            // B*T
#define NCHUNK 72
#define CHUNK 16384
#define TILEP 32
#define NTILE 288         // HW_/TILEP

typedef unsigned long long ull;

__device__ __forceinline__ ull pack2(float a, float b) {
    ull r; asm("mov.b64 %0,{%1,%2};" : "=l"(r) : "f"(a), "f"(b)); return r;
}
__device__ __forceinline__ ull fma2(ull a, ull b, ull c) {
    ull d; asm("fma.rn.f32x2 %0,%1,%2,%3;" : "=l"(d) : "l"(a), "l"(b), "l"(c)); return d;
}
__device__ __forceinline__ ull mul2(ull a, ull b) {
    ull d; asm("mul.rn.f32x2 %0,%1,%2;" : "=l"(d) : "l"(a), "l"(b)); return d;
}

// deterministic scratch
__device__ float g_psum[NBT * NCHUNK];
__device__ float g_psq [NBT * NCHUNK];
__device__ float g_A[NBT * C_];
__device__ float g_Bc[NBT * C_];
__device__ float g_WkT[C_ * C_];   // [c][h*32+d] = qkv_w[128 + h*32+d][c] * scale

// ---------------- Kernel 1: partial sums per (b,t) chunk ----------------
__global__ __launch_bounds__(256) void reduce_kernel(const float* __restrict__ x,
                                                     const float* __restrict__ pos) {
    int bt    = blockIdx.x / NCHUNK;
    int chunk = blockIdx.x % NCHUNK;
    int t     = bt & (T_ - 1);
    const float4* x4 = (const float4*)(x + (size_t)bt * C_ * HW_);
    int base4 = chunk * (CHUNK / 4);
    float s = 0.f, sq = 0.f;
#pragma unroll
    for (int i = 0; i < 16; i++) {
        int e4 = base4 + i * 256 + threadIdx.x;
        int c  = e4 / 2304;
        float pv = pos[t * C_ + c];
        float4 v = x4[e4];
        float a0 = v.x + pv, a1 = v.y + pv, a2 = v.z + pv, a3 = v.w + pv;
        s  += (a0 + a1) + (a2 + a3);
        sq += (a0 * a0 + a1 * a1) + (a2 * a2 + a3 * a3);
    }
    __shared__ float ss[8], ssq[8];
#pragma unroll
    for (int o = 16; o; o >>= 1) {
        s  += __shfl_down_sync(0xFFFFFFFFu, s, o);
        sq += __shfl_down_sync(0xFFFFFFFFu, sq, o);
    }
    int w = threadIdx.x >> 5;
    if ((threadIdx.x & 31) == 0) { ss[w] = s; ssq[w] = sq; }
    __syncthreads();
    if (threadIdx.x == 0) {
        float S = 0.f, SQ = 0.f;
#pragma unroll
        for (int i = 0; i < 8; i++) { S += ss[i]; SQ += ssq[i]; }
        g_psum[bt * NCHUNK + chunk] = S;
        g_psq [bt * NCHUNK + chunk] = SQ;
    }
}

// ---------------- Kernel 2: finalize mean/rstd -> affine A,B ----------------
__global__ __launch_bounds__(256) void finalize_kernel(const float* __restrict__ pos,
                                                       const float* __restrict__ nw,
                                                       const float* __restrict__ nb) {
    __shared__ float sm[NBT], sr[NBT];
    int tid = threadIdx.x;
    if (tid < NBT) {
        float S = 0.f, SQ = 0.f;
        for (int i = 0; i < NCHUNK; i++) { S += g_psum[tid * NCHUNK + i]; SQ += g_psq[tid * NCHUNK + i]; }
        const float invN = 1.0f / (float)(C_ * HW_);
        float mean = S * invN;
        float var  = SQ * invN - mean * mean;
        sm[tid] = mean;
        sr[tid] = rsqrtf(var + 1e-5f);
    }
    __syncthreads();
    for (int idx = tid; idx < NBT * C_; idx += 256) {
        int bt = idx >> 7, c = idx & 127, t = bt & (T_ - 1);
        float a = sr[bt] * nw[c];
        g_A[idx]  = a;
        g_Bc[idx] = (pos[t * C_ + c] - sm[bt]) * a + nb[c];
    }
}

// ---------------- Kernel 2b: transpose Wk (attention scale folded in) ----------------
__global__ __launch_bounds__(256) void wkT_kernel(const float* __restrict__ qkv_w) {
    int i = blockIdx.x * 256 + threadIdx.x;   // 0..16383
    int c = i >> 7, hd = i & 127;
    g_WkT[c * 128 + hd] = qkv_w[(128 + hd) * 128 + c] * 0.17677669529663687f;
}

// ---------------- Kernel 3: fused main ----------------
// smem float offsets
#define SM_XN   0                     // 128*32 = 4096
#define SM_BIG  4096                  // 4*128*32 = 16384  (U, then XBAR)
#define SM_Q    20480                 // 128*32 = 4096 (Q, then logit partials, then Out)
#define SM_WS   24576                 // 128
#define SM_CORR 24704                 // 128
#define SMEM_FLOATS 24832
#define SMEM_BYTES (SMEM_FLOATS * 4)  // 99328

// 4-output-row x 32-pixel packed GEMM core; x rows stride 32, w rows stride 128
__device__ __forceinline__ void gemm_core(const float* __restrict__ wrow,
                                          const float* __restrict__ xsrc,
                                          int pg, int kdim, ull acc[4][2]) {
#pragma unroll
    for (int i = 0; i < 4; i++) { acc[i][0] = 0ull; acc[i][1] = 0ull; }
#pragma unroll 4
    for (int k = 0; k < kdim; k += 4) {
        ull xv[4][2];
#pragma unroll
        for (int kk = 0; kk < 4; kk++) {
            ulonglong2 v = *(const ulonglong2*)(xsrc + (k + kk) * 32 + pg * 4);
            xv[kk][0] = v.x; xv[kk][1] = v.y;
        }
#pragma unroll
        for (int i = 0; i < 4; i++) {
            float4 wv = *(const float4*)(wrow + i * C_ + k);
            ull w0 = pack2(wv.x, wv.x), w1 = pack2(wv.y, wv.y);
            ull w2 = pack2(wv.z, wv.z), w3 = pack2(wv.w, wv.w);
            acc[i][0] = fma2(w0, xv[0][0], acc[i][0]); acc[i][1] = fma2(w0, xv[0][1], acc[i][1]);
            acc[i][0] = fma2(w1, xv[1][0], acc[i][0]); acc[i][1] = fma2(w1, xv[1][1], acc[i][1]);
            acc[i][0] = fma2(w2, xv[2][0], acc[i][0]); acc[i][1] = fma2(w2, xv[2][1], acc[i][1]);
            acc[i][0] = fma2(w3, xv[3][0], acc[i][0]); acc[i][1] = fma2(w3, xv[3][1], acc[i][1]);
        }
    }
}

__global__ __launch_bounds__(256, 2) void main_kernel(const float* __restrict__ x,
                                                      const float* __restrict__ qkv_w,
                                                      const float* __restrict__ proj_w,
                                                      float* __restrict__ out) {
    extern __shared__ float sm[];
    float* sXN   = sm + SM_XN;
    float* sBig  = sm + SM_BIG;
    float* sQ    = sm + SM_Q;
    float* sWs   = sm + SM_WS;
    float* sCorr = sm + SM_CORR;

    int b    = blockIdx.x / NTILE;
    int tile = blockIdx.x % NTILE;
    int hw0  = tile * TILEP;
    int tid  = threadIdx.x;
    int cg   = tid >> 3;   // 0..31
    int pg   = tid & 7;    // 0..7
    int cld  = tid >> 5;   // refill: base c
    int pld  = tid & 31;   // refill: pixel

    // ---- Phase A: normalized tile at t=T-1 ----
    {
        int bt = b * T_ + (T_ - 1);
        const float* xb = x + (size_t)bt * C_ * HW_;
        const float* Ab = g_A  + bt * C_;
        const float* Bb = g_Bc + bt * C_;
#pragma unroll
        for (int j = 0; j < 16; j++) {
            int c = cld + j * 8;
            sXN[c * 32 + pld] = xb[c * HW_ + hw0 + pld] * Ab[c] + Bb[c];
        }
    }
    __syncthreads();

    // prefetch t=0 (overlaps Q and U GEMMs)
    float xr[16];
    {
        const float* xb = x + (size_t)(b * T_) * C_ * HW_;
#pragma unroll
        for (int j = 0; j < 16; j++) xr[j] = xb[(cld + j * 8) * HW_ + hw0 + pld];
    }

    // ---- Q GEMM (unscaled; scale folded into WkT) -> sQ ----
    {
        ull acc[4][2];
        gemm_core(qkv_w + (size_t)(cg * 4) * C_, sXN, pg, 128, acc);
#pragma unroll
        for (int i = 0; i < 4; i++) {
            ulonglong2 o; o.x = acc[i][0]; o.y = acc[i][1];
            *(ulonglong2*)(sQ + (cg * 4 + i) * 32 + pg * 4) = o;
        }
    }
    __syncthreads();

    // ---- U_h[c][p] = sum_d WkT[c][h*32+d]*Q[h*32+d][p] -> sBig ----
#pragma unroll
    for (int h = 0; h < 4; h++) {
        ull acc[4][2];
        gemm_core(g_WkT + (size_t)(cg * 4) * C_ + h * 32, sQ + h * 1024, pg, 32, acc);
#pragma unroll
        for (int i = 0; i < 4; i++) {
            ulonglong2 o; o.x = acc[i][0]; o.y = acc[i][1];
            *(ulonglong2*)(sBig + h * 4096 + (cg * 4 + i) * 32 + pg * 4) = o;
        }
    }
    __syncthreads();

    // ---- online-softmax main loop: s order 7,0,1,...,6 (x read ONCE) ----
    int   h0  = (tid >> 7) << 1;      // xbar mapping: head pair
    int   cgx = (tid >> 3) & 15;      // 8 c-rows
    int   pgl = tid & 7;
    ull   xbv[2][8][2];
#pragma unroll
    for (int h2 = 0; h2 < 2; h2++)
#pragma unroll
        for (int cc = 0; cc < 8; cc++) { xbv[h2][cc][0] = 0ull; xbv[h2][cc][1] = 0ull; }
    float m_run = -1e30f, s_run = 0.f;

    for (int it = 0; it < T_; it++) {
        int s = (it == 0) ? (T_ - 1) : (it - 1);
        if (it > 0) {
            __syncthreads();   // previous xbar update done reading sXN
            int bt = b * T_ + s;
            const float* Ab = g_A  + bt * C_;
            const float* Bb = g_Bc + bt * C_;
#pragma unroll
            for (int j = 0; j < 16; j++) {
                int c = cld + j * 8;
                sXN[c * 32 + pld] = xr[j] * Ab[c] + Bb[c];
            }
        }
        __syncthreads();       // sXN ready, sQ free for partials
        if (it < T_ - 1) {     // prefetch next s (= it)
            const float* xb = x + (size_t)(b * T_ + it) * C_ * HW_;
#pragma unroll
            for (int j = 0; j < 16; j++) xr[j] = xb[(cld + j * 8) * HW_ + hw0 + pld];
        }

        // logit partials over this thread's 4 c-rows (both operands pixel-packed)
        {
            ull lg[4][2];
#pragma unroll
            for (int h = 0; h < 4; h++) { lg[h][0] = 0ull; lg[h][1] = 0ull; }
#pragma unroll
            for (int ccc = 0; ccc < 4; ccc++) {
                int c = cg * 4 + ccc;
                ulonglong2 xv = *(const ulonglong2*)(sXN + c * 32 + pg * 4);
#pragma unroll
                for (int h = 0; h < 4; h++) {
                    ulonglong2 uv = *(const ulonglong2*)(sBig + h * 4096 + c * 32 + pg * 4);
                    lg[h][0] = fma2(xv.x, uv.x, lg[h][0]);
                    lg[h][1] = fma2(xv.y, uv.y, lg[h][1]);
                }
            }
#pragma unroll
            for (int h = 0; h < 4; h++) {
                ulonglong2 o; o.x = lg[h][0]; o.y = lg[h][1];
                *(ulonglong2*)(sQ + cg * 128 + h * 32 + pg * 4) = o;
            }
        }
        __syncthreads();

        // reduce partials + online softmax state (threads 0..127 = h*32+p)
        if (tid < 128) {
            float L0 = 0.f, L1 = 0.f, L2 = 0.f, L3 = 0.f;
#pragma unroll
            for (int g2 = 0; g2 < 32; g2 += 4) {
                L0 += sQ[(g2    ) * 128 + tid];
                L1 += sQ[(g2 + 1) * 128 + tid];
                L2 += sQ[(g2 + 2) * 128 + tid];
                L3 += sQ[(g2 + 3) * 128 + tid];
            }
            float L  = (L0 + L1) + (L2 + L3);
            float mn = fmaxf(m_run, L);
            float corr = expf(m_run - mn);
            float e    = expf(L - mn);
            s_run = s_run * corr + e;
            m_run = mn;
            sWs[tid]   = e;
            sCorr[tid] = corr;
        }
        __syncthreads();

        // xbar update: xbar = xbar*corr + ws*xn  (all operands pixel-packed)
        {
            ulonglong2 xvs[8];
#pragma unroll
            for (int cc = 0; cc < 8; cc++)
                xvs[cc] = *(const ulonglong2*)(sXN + (cgx * 8 + cc) * 32 + pgl * 4);
#pragma unroll
            for (int h2 = 0; h2 < 2; h2++) {
                ulonglong2 wv = *(const ulonglong2*)(sWs   + (h0 + h2) * 32 + pgl * 4);
                ulonglong2 cv = *(const ulonglong2*)(sCorr + (h0 + h2) * 32 + pgl * 4);
#pragma unroll
                for (int cc = 0; cc < 8; cc++) {
                    xbv[h2][cc][0] = fma2(wv.x, xvs[cc].x, mul2(cv.x, xbv[h2][cc][0]));
                    xbv[h2][cc][1] = fma2(wv.y, xvs[cc].y, mul2(cv.y, xbv[h2][cc][1]));
                }
            }
        }
    }
    __syncthreads();

    // normalize xbar by softmax denominator and store into sBig (U dead)
    if (tid < 128) sWs[tid] = 1.0f / s_run;
    __syncthreads();
#pragma unroll
    for (int h2 = 0; h2 < 2; h2++) {
        ulonglong2 iv = *(const ulonglong2*)(sWs + (h0 + h2) * 32 + pgl * 4);
#pragma unroll
        for (int cc = 0; cc < 8; cc++) {
            ulonglong2 o;
            o.x = mul2(iv.x, xbv[h2][cc][0]);
            o.y = mul2(iv.y, xbv[h2][cc][1]);
            *(ulonglong2*)(sBig + (h0 + h2) * 4096 + (cgx * 8 + cc) * 32 + pgl * 4) = o;
        }
    }
    __syncthreads();

    // ---- Phase E: Out[hd][p] = Wv . xbar_h -> sQ ----
    {
        ull acc[4][2];
        gemm_core(qkv_w + (size_t)(256 + cg * 4) * C_, sBig + (cg >> 3) * 4096, pg, 128, acc);
#pragma unroll
        for (int i = 0; i < 4; i++) {
            ulonglong2 o; o.x = acc[i][0]; o.y = acc[i][1];
            *(ulonglong2*)(sQ + (cg * 4 + i) * 32 + pg * 4) = o;
        }
    }
    __syncthreads();

    // ---- Phase F: projection -> gmem ----
    {
        ull acc[4][2];
        gemm_core(proj_w + (size_t)(cg * 4) * C_, sQ, pg, 128, acc);
#pragma unroll
        for (int i = 0; i < 4; i++) {
            ulonglong2 o; o.x = acc[i][0]; o.y = acc[i][1];
            *(ulonglong2*)(out + ((size_t)b * C_ + cg * 4 + i) * HW_ + hw0 + pg * 4) = o;
        }
    }
}

extern "C" void kernel_launch(void* const* d_in, const int* in_sizes, int n_in,
                              void* d_out, int out_size) {
    const float* x    = (const float*)d_in[0];
    const float* pos  = (const float*)d_in[1];
    const float* nw   = (const float*)d_in[2];
    const float* nb   = (const float*)d_in[3];
    const float* qkvw = (const float*)d_in[4];
    const float* pw   = (const float*)d_in[5];
    float* out = (float*)d_out;

    reduce_kernel<<<NBT * NCHUNK, 256>>>(x, pos);
    finalize_kernel<<<1, 256>>>(pos, nw, nb);
    wkT_kernel<<<64, 256>>>(qkvw);
    cudaFuncSetAttribute(main_kernel, cudaFuncAttributeMaxDynamicSharedMemorySize, SMEM_BYTES);
    main_kernel<<<B_ * NTILE, 256, SMEM_BYTES>>>(x, qkvw, pw, out);
}

// round 4
// speedup vs baseline: 3.0203x; 1.0154x over previous
#include <cuda_runtime.h>
#include <math.h>

#define B_ 4
#define T_ 8
#define C_ 128
#define HW_ 9216          // 96*96
#define NBT 32            // B*T
#define NCHUNK 72
#define CHUNK 16384
#define TILEP 32
#define NTILE 288         // HW_/TILEP

typedef unsigned long long ull;

__device__ __forceinline__ ull pack2(float a, float b) {
    ull r; asm("mov.b64 %0,{%1,%2};" : "=l"(r) : "f"(a), "f"(b)); return r;
}
__device__ __forceinline__ void unpack2(ull v, float& a, float& b) {
    asm("mov.b64 {%0,%1},%2;" : "=f"(a), "=f"(b) : "l"(v));
}
__device__ __forceinline__ ull fma2(ull a, ull b, ull c) {
    ull d; asm("fma.rn.f32x2 %0,%1,%2,%3;" : "=l"(d) : "l"(a), "l"(b), "l"(c)); return d;
}
__device__ __forceinline__ ull mul2(ull a, ull b) {
    ull d; asm("mul.rn.f32x2 %0,%1,%2;" : "=l"(d) : "l"(a), "l"(b)); return d;
}

// deterministic scratch
__device__ float g_psum[NBT * NCHUNK];
__device__ float g_psq [NBT * NCHUNK];
__device__ float g_A[NBT * C_];
__device__ float g_Bc[NBT * C_];
__device__ float g_WkT[C_ * C_];   // [c][h*32+d] = qkv_w[128 + h*32+d][c] * scale

// ---------------- Kernel 1: partial sums per (b,t) chunk ----------------
__global__ __launch_bounds__(256) void reduce_kernel(const float* __restrict__ x,
                                                     const float* __restrict__ pos) {
    int bt    = blockIdx.x / NCHUNK;
    int chunk = blockIdx.x % NCHUNK;
    int t     = bt & (T_ - 1);
    const float4* x4 = (const float4*)(x + (size_t)bt * C_ * HW_);
    int base4 = chunk * (CHUNK / 4);
    float s = 0.f, sq = 0.f;
#pragma unroll
    for (int i = 0; i < 16; i++) {
        int e4 = base4 + i * 256 + threadIdx.x;
        int c  = e4 / 2304;
        float pv = pos[t * C_ + c];
        float4 v = x4[e4];
        float a0 = v.x + pv, a1 = v.y + pv, a2 = v.z + pv, a3 = v.w + pv;
        s  += (a0 + a1) + (a2 + a3);
        sq += (a0 * a0 + a1 * a1) + (a2 * a2 + a3 * a3);
    }
    __shared__ float ss[8], ssq[8];
#pragma unroll
    for (int o = 16; o; o >>= 1) {
        s  += __shfl_down_sync(0xFFFFFFFFu, s, o);
        sq += __shfl_down_sync(0xFFFFFFFFu, sq, o);
    }
    int w = threadIdx.x >> 5;
    if ((threadIdx.x & 31) == 0) { ss[w] = s; ssq[w] = sq; }
    __syncthreads();
    if (threadIdx.x == 0) {
        float S = 0.f, SQ = 0.f;
#pragma unroll
        for (int i = 0; i < 8; i++) { S += ss[i]; SQ += ssq[i]; }
        g_psum[bt * NCHUNK + chunk] = S;
        g_psq [bt * NCHUNK + chunk] = SQ;
    }
}

// ---------------- Kernel 2: finalize mean/rstd -> affine A,B ----------------
__global__ __launch_bounds__(256) void finalize_kernel(const float* __restrict__ pos,
                                                       const float* __restrict__ nw,
                                                       const float* __restrict__ nb) {
    __shared__ float sm[NBT], sr[NBT];
    int tid = threadIdx.x;
    if (tid < NBT) {
        float S = 0.f, SQ = 0.f;
        for (int i = 0; i < NCHUNK; i++) { S += g_psum[tid * NCHUNK + i]; SQ += g_psq[tid * NCHUNK + i]; }
        const float invN = 1.0f / (float)(C_ * HW_);
        float mean = S * invN;
        float var  = SQ * invN - mean * mean;
        sm[tid] = mean;
        sr[tid] = rsqrtf(var + 1e-5f);
    }
    __syncthreads();
    for (int idx = tid; idx < NBT * C_; idx += 256) {
        int bt = idx >> 7, c = idx & 127, t = bt & (T_ - 1);
        float a = sr[bt] * nw[c];
        g_A[idx]  = a;
        g_Bc[idx] = (pos[t * C_ + c] - sm[bt]) * a + nb[c];
    }
}

// ---------------- Kernel 2b: transpose Wk (attention scale folded in) ----------------
__global__ __launch_bounds__(256) void wkT_kernel(const float* __restrict__ qkv_w) {
    int i = blockIdx.x * 256 + threadIdx.x;   // 0..16383
    int c = i >> 7, hd = i & 127;
    g_WkT[c * 128 + hd] = qkv_w[(128 + hd) * 128 + c] * 0.17677669529663687f;
}

// ---------------- Kernel 3: fused main ----------------
// smem float offsets
#define SM_XN   0                     // 128*32 = 4096 (t=7 tile only)
#define SM_BIG  4096                  // 4*128*32 = 16384 (U, then XBAR)
#define SM_Q    20480                 // 128*32 = 4096 (Q, then Out)
#define SM_P    24576                 // 1024 (logit partials, float4 per (cld,pld))
#define SM_AB   25600                 // 2048 (A then B, [t*128+c])
#define SMEM_FLOATS 27648
#define SMEM_BYTES (SMEM_FLOATS * 4)  // 110592

// 4-output-row x 32-pixel packed GEMM core; x rows stride 32, w rows stride 128
__device__ __forceinline__ void gemm_core(const float* __restrict__ wrow,
                                          const float* __restrict__ xsrc,
                                          int pg, int kdim, ull acc[4][2]) {
#pragma unroll
    for (int i = 0; i < 4; i++) { acc[i][0] = 0ull; acc[i][1] = 0ull; }
#pragma unroll 4
    for (int k = 0; k < kdim; k += 4) {
        ull xv[4][2];
#pragma unroll
        for (int kk = 0; kk < 4; kk++) {
            ulonglong2 v = *(const ulonglong2*)(xsrc + (k + kk) * 32 + pg * 4);
            xv[kk][0] = v.x; xv[kk][1] = v.y;
        }
#pragma unroll
        for (int i = 0; i < 4; i++) {
            float4 wv = *(const float4*)(wrow + i * C_ + k);
            ull w0 = pack2(wv.x, wv.x), w1 = pack2(wv.y, wv.y);
            ull w2 = pack2(wv.z, wv.z), w3 = pack2(wv.w, wv.w);
            acc[i][0] = fma2(w0, xv[0][0], acc[i][0]); acc[i][1] = fma2(w0, xv[0][1], acc[i][1]);
            acc[i][0] = fma2(w1, xv[1][0], acc[i][0]); acc[i][1] = fma2(w1, xv[1][1], acc[i][1]);
            acc[i][0] = fma2(w2, xv[2][0], acc[i][0]); acc[i][1] = fma2(w2, xv[2][1], acc[i][1]);
            acc[i][0] = fma2(w3, xv[3][0], acc[i][0]); acc[i][1] = fma2(w3, xv[3][1], acc[i][1]);
        }
    }
}

__global__ __launch_bounds__(256, 1) void main_kernel(const float* __restrict__ x,
                                                      const float* __restrict__ qkv_w,
                                                      const float* __restrict__ proj_w,
                                                      float* __restrict__ out) {
    extern __shared__ float sm[];
    float* sXN  = sm + SM_XN;
    float* sBig = sm + SM_BIG;
    float* sQ   = sm + SM_Q;
    float* sP   = sm + SM_P;
    float* sAB  = sm + SM_AB;

    int b    = blockIdx.x / NTILE;
    int tile = blockIdx.x % NTILE;
    int hw0  = tile * TILEP;
    int tid  = threadIdx.x;
    int cg   = tid >> 3;   // GEMM layout: 0..31
    int pg   = tid & 7;    // GEMM layout: 0..7
    int cld  = tid >> 5;   // attention layout: warp id 0..7 (c-set {cld+8j})
    int pld  = tid & 31;   // attention layout: pixel

    // ---- stage A/B affine tables for this b ----
    for (int idx = tid; idx < 1024; idx += 256) {
        sAB[idx]        = g_A [b * T_ * C_ + idx];
        sAB[1024 + idx] = g_Bc[b * T_ * C_ + idx];
    }

    // ---- Phase A: normalized tile at t=T-1 ----
    {
        int bt = b * T_ + (T_ - 1);
        const float* xb = x + (size_t)bt * C_ * HW_;
        const float* Ab = g_A  + bt * C_;
        const float* Bb = g_Bc + bt * C_;
#pragma unroll
        for (int j = 0; j < 16; j++) {
            int c = cld + j * 8;
            sXN[c * 32 + pld] = xb[c * HW_ + hw0 + pld] * Ab[c] + Bb[c];
        }
    }
    __syncthreads();

    // prefetch t=0 raw x (overlaps Q and U GEMMs)
    float xr[16];
    {
        const float* xb = x + (size_t)(b * T_) * C_ * HW_;
#pragma unroll
        for (int j = 0; j < 16; j++) xr[j] = xb[(cld + j * 8) * HW_ + hw0 + pld];
    }

    // ---- Q GEMM (scale folded into WkT) -> sQ ----
    {
        ull acc[4][2];
        gemm_core(qkv_w + (size_t)(cg * 4) * C_, sXN, pg, 128, acc);
#pragma unroll
        for (int i = 0; i < 4; i++) {
            ulonglong2 o; o.x = acc[i][0]; o.y = acc[i][1];
            *(ulonglong2*)(sQ + (cg * 4 + i) * 32 + pg * 4) = o;
        }
    }
    __syncthreads();

    // ---- U_h[c][p] = sum_d WkT[c][h*32+d]*Q[h*32+d][p] -> sBig ----
#pragma unroll
    for (int h = 0; h < 4; h++) {
        ull acc[4][2];
        gemm_core(g_WkT + (size_t)(cg * 4) * C_ + h * 32, sQ + h * 1024, pg, 32, acc);
#pragma unroll
        for (int i = 0; i < 4; i++) {
            ulonglong2 o; o.x = acc[i][0]; o.y = acc[i][1];
            *(ulonglong2*)(sBig + h * 4096 + (cg * 4 + i) * 32 + pg * 4) = o;
        }
    }
    __syncthreads();

    // ---- load U into registers (attention layout), packed over c-pairs (c, c+8) ----
    ull uP[4][8];
#pragma unroll
    for (int h = 0; h < 4; h++)
#pragma unroll
        for (int jj = 0; jj < 8; jj++) {
            float a0 = sBig[h * 4096 + (cld + 16 * jj    ) * 32 + pld];
            float a1 = sBig[h * 4096 + (cld + 16 * jj + 8) * 32 + pld];
            uP[h][jj] = pack2(a0, a1);
        }

    // xn for t=7 from sXN, packed same way
    ull xnP[8];
#pragma unroll
    for (int jj = 0; jj < 8; jj++) {
        float a0 = sXN[(cld + 16 * jj    ) * 32 + pld];
        float a1 = sXN[(cld + 16 * jj + 8) * 32 + pld];
        xnP[jj] = pack2(a0, a1);
    }

    // register-resident online softmax + xbar accumulation
    ull   xbarP[4][8];
#pragma unroll
    for (int h = 0; h < 4; h++)
#pragma unroll
        for (int jj = 0; jj < 8; jj++) xbarP[h][jj] = 0ull;
    float m_run[4] = {-1e30f, -1e30f, -1e30f, -1e30f};
    float s_run[4] = {0.f, 0.f, 0.f, 0.f};

    for (int it = 0; it < T_; it++) {
        int s = (it == 0) ? (T_ - 1) : (it - 1);
        if (it > 0) {
            // normalize xr -> xnP (registers only)
            const float* As = sAB + s * 128;
            const float* Bs = sAB + 1024 + s * 128;
#pragma unroll
            for (int jj = 0; jj < 8; jj++) {
                int c0 = cld + 16 * jj;
                float a0 = xr[2 * jj]     * As[c0]     + Bs[c0];
                float a1 = xr[2 * jj + 1] * As[c0 + 8] + Bs[c0 + 8];
                xnP[jj] = pack2(a0, a1);
            }
        }
        if (it >= 1 && it < T_ - 1) {   // prefetch raw x for t=it (used next iter)
            const float* xb = x + (size_t)(b * T_ + it) * C_ * HW_;
#pragma unroll
            for (int jj = 0; jj < 8; jj++) {
                xr[2 * jj]     = xb[(cld + 16 * jj    ) * HW_ + hw0 + pld];
                xr[2 * jj + 1] = xb[(cld + 16 * jj + 8) * HW_ + hw0 + pld];
            }
        }

        // logit partials over this thread's 16 c (pure register fma2)
        ull lg[4] = {0ull, 0ull, 0ull, 0ull};
#pragma unroll
        for (int jj = 0; jj < 8; jj++) {
            lg[0] = fma2(xnP[jj], uP[0][jj], lg[0]);
            lg[1] = fma2(xnP[jj], uP[1][jj], lg[1]);
            lg[2] = fma2(xnP[jj], uP[2][jj], lg[2]);
            lg[3] = fma2(xnP[jj], uP[3][jj], lg[3]);
        }
        float4 part;
        { float lo, hi;
          unpack2(lg[0], lo, hi); part.x = lo + hi;
          unpack2(lg[1], lo, hi); part.y = lo + hi;
          unpack2(lg[2], lo, hi); part.z = lo + hi;
          unpack2(lg[3], lo, hi); part.w = lo + hi; }
        *(float4*)(sP + (cld * 32 + pld) * 4) = part;
        __syncthreads();

        // reduce 8 partials (all threads of a pixel do it redundantly, identically)
        float L[4] = {0.f, 0.f, 0.f, 0.f};
#pragma unroll
        for (int k = 0; k < 8; k++) {
            float4 v = *(const float4*)(sP + (k * 32 + pld) * 4);
            L[0] += v.x; L[1] += v.y; L[2] += v.z; L[3] += v.w;
        }
        __syncthreads();   // sP free for next iteration

        // per-head softmax state + xbar update (registers only)
#pragma unroll
        for (int h = 0; h < 4; h++) {
            float mn   = fmaxf(m_run[h], L[h]);
            float corr = expf(m_run[h] - mn);
            float e    = expf(L[h] - mn);
            s_run[h] = s_run[h] * corr + e;
            m_run[h] = mn;
            ull cP = pack2(corr, corr);
            ull eP = pack2(e, e);
#pragma unroll
            for (int jj = 0; jj < 8; jj++)
                xbarP[h][jj] = fma2(eP, xnP[jj], mul2(cP, xbarP[h][jj]));
        }
    }

    // normalize xbar and write to sBig (U no longer needed)
#pragma unroll
    for (int h = 0; h < 4; h++) {
        float inv = 1.0f / s_run[h];
        ull iP = pack2(inv, inv);
#pragma unroll
        for (int jj = 0; jj < 8; jj++) {
            float lo, hi;
            unpack2(mul2(iP, xbarP[h][jj]), lo, hi);
            sBig[h * 4096 + (cld + 16 * jj    ) * 32 + pld] = lo;
            sBig[h * 4096 + (cld + 16 * jj + 8) * 32 + pld] = hi;
        }
    }
    __syncthreads();

    // ---- Phase E: Out[hd][p] = Wv . xbar_h -> sQ ----
    {
        ull acc[4][2];
        gemm_core(qkv_w + (size_t)(256 + cg * 4) * C_, sBig + (cg >> 3) * 4096, pg, 128, acc);
#pragma unroll
        for (int i = 0; i < 4; i++) {
            ulonglong2 o; o.x = acc[i][0]; o.y = acc[i][1];
            *(ulonglong2*)(sQ + (cg * 4 + i) * 32 + pg * 4) = o;
        }
    }
    __syncthreads();

    // ---- Phase F: projection -> gmem ----
    {
        ull acc[4][2];
        gemm_core(proj_w + (size_t)(cg * 4) * C_, sQ, pg, 128, acc);
#pragma unroll
        for (int i = 0; i < 4; i++) {
            ulonglong2 o; o.x = acc[i][0]; o.y = acc[i][1];
            *(ulonglong2*)(out + ((size_t)b * C_ + cg * 4 + i) * HW_ + hw0 + pg * 4) = o;
        }
    }
}

extern "C" void kernel_launch(void* const* d_in, const int* in_sizes, int n_in,
                              void* d_out, int out_size) {
    const float* x    = (const float*)d_in[0];
    const float* pos  = (const float*)d_in[1];
    const float* nw   = (const float*)d_in[2];
    const float* nb   = (const float*)d_in[3];
    const float* qkvw = (const float*)d_in[4];
    const float* pw   = (const float*)d_in[5];
    float* out = (float*)d_out;

    reduce_kernel<<<NBT * NCHUNK, 256>>>(x, pos);
    finalize_kernel<<<1, 256>>>(pos, nw, nb);
    wkT_kernel<<<64, 256>>>(qkvw);
    cudaFuncSetAttribute(main_kernel, cudaFuncAttributeMaxDynamicSharedMemorySize, SMEM_BYTES);
    main_kernel<<<B_ * NTILE, 256, SMEM_BYTES>>>(x, qkvw, pw, out);
}